// round 15
// baseline (speedup 1.0000x reference)
#include <cuda_runtime.h>
#include <math.h>
#include <stdint.h>

// ---------------- problem constants ----------------
#define D128 128
#define BGR 64
#define NPG0 1024
#define NMAX (BGR * NPG0)        // 65536
#define EMAX 1048576
#define K1 820
#define K2 656
#define K3 525

// ---------------- scratch ----------------
__device__ float g_mean[NMAX * D128];
__device__ float g_h[NMAX * D128];
__device__ float g_poolA[BGR * K1 * D128];
__device__ float g_poolB[BGR * K2 * D128];
__device__ float g_score[NMAX];
__device__ int   g_newid[NMAX];
__device__ int   g_orig2cur[NMAX];
__device__ int   g_cur2orig[NMAX];
__device__ int   g_rowptr[NMAX + 1];
__device__ int   g_nbr[EMAX];
__device__ float g_bhi[3][256 * D128];
__device__ float g_blo[3][256 * D128];
__device__ float g_s[BGR * 256];

__device__ __forceinline__ void tf32_split(float v, uint32_t& hi, uint32_t& lo) {
    asm("cvt.rna.tf32.f32 %0, %1;" : "=r"(hi) : "f"(v));
    float r = v - __uint_as_float(hi);
    asm("cvt.rna.tf32.f32 %0, %1;" : "=r"(lo) : "f"(r));
}

__device__ __forceinline__ void mma_m16n8k8(float* c, const uint32_t* a, const uint32_t* b) {
    asm volatile(
        "mma.sync.aligned.m16n8k8.row.col.f32.tf32.tf32.f32 "
        "{%0,%1,%2,%3}, {%4,%5,%6,%7}, {%8,%9}, {%0,%1,%2,%3};"
        : "+f"(c[0]), "+f"(c[1]), "+f"(c[2]), "+f"(c[3])
        : "r"(a[0]), "r"(a[1]), "r"(a[2]), "r"(a[3]), "r"(b[0]), "r"(b[1]));
}

__device__ __forceinline__ void split4(float4 v, float4& hv, float4& lv) {
    uint32_t h0, h1, h2, h3, l0, l1, l2, l3;
    tf32_split(v.x, h0, l0); tf32_split(v.y, h1, l1);
    tf32_split(v.z, h2, l2); tf32_split(v.w, h3, l3);
    hv = make_float4(__uint_as_float(h0), __uint_as_float(h1),
                     __uint_as_float(h2), __uint_as_float(h3));
    lv = make_float4(__uint_as_float(l0), __uint_as_float(l1),
                     __uint_as_float(l2), __uint_as_float(l3));
}

// ---------------- init: CSR (blocks 0..63) + weight split (blocks 64..159) ----------------
__global__ void __launch_bounds__(1024)
k_init(const int* __restrict__ src, const int* __restrict__ dst, int epg,
       int* __restrict__ rowptr, int* __restrict__ nbr,
       int* __restrict__ o2c, int* __restrict__ c2o,
       const float* __restrict__ Wl1, const float* __restrict__ Wr1,
       const float* __restrict__ Wl2, const float* __restrict__ Wr2,
       const float* __restrict__ Wl3, const float* __restrict__ Wr3,
       float* __restrict__ bh, float* __restrict__ bl) {
    __shared__ int deg[1024];
    __shared__ int cur[1024];
    int t = threadIdx.x;
    if (blockIdx.x >= BGR) {
        int i = (blockIdx.x - BGR) * 1024 + t;   // 0..98303
        int l = i >> 15, j = i & 32767;
        const float* Wl = (l == 0) ? Wl1 : (l == 1) ? Wl2 : Wl3;
        const float* Wr = (l == 0) ? Wr1 : (l == 1) ? Wr2 : Wr3;
        float v = (j < 16384) ? Wl[j] : Wr[j - 16384];
        uint32_t hi, lo;
        tf32_split(v, hi, lo);
        bh[i] = __uint_as_float(hi);
        bl[i] = __uint_as_float(lo);
        return;
    }
    int g = blockIdx.x;
    int ebase = g * epg;
    int nbase = g * NPG0;

    deg[t] = 0;
    __syncthreads();
    for (int e = ebase + t; e < ebase + epg; e += 1024)
        atomicAdd(&deg[dst[e] - nbase], 1);
    __syncthreads();
    int my = deg[t];
    cur[t] = my;
    __syncthreads();
    for (int off = 1; off < 1024; off <<= 1) {
        int v = cur[t];
        if (t >= off) v += cur[t - off];
        __syncthreads();
        cur[t] = v;
        __syncthreads();
    }
    int ex = cur[t] - my;
    rowptr[nbase + t] = ebase + ex;
    o2c[nbase + t] = nbase + t;
    c2o[nbase + t] = nbase + t;
    if (g == 0 && t == 0) rowptr[NMAX] = BGR * epg;
    __syncthreads();
    cur[t] = ex;
    __syncthreads();
    for (int e = ebase + t; e < ebase + epg; e += 1024) {
        int d = dst[e] - nbase;
        int p = atomicAdd(&cur[d], 1);
        nbr[ebase + p] = src[e];
    }
}

// ---------------- mean aggregation ----------------
__global__ void k_aggregate1(const float* __restrict__ X, const int* __restrict__ rowptr,
                             const int* __restrict__ nbr, float* __restrict__ mean, int n) {
    int w = (blockIdx.x * blockDim.x + threadIdx.x) >> 5;
    int lane = threadIdx.x & 31;
    if (w >= n) return;
    int b = rowptr[w], e = rowptr[w + 1];
    float4 acc = make_float4(0.f, 0.f, 0.f, 0.f);
#pragma unroll 4
    for (int j = b; j < e; j++) {
        float4 v = ((const float4*)(X + (size_t)nbr[j] * D128))[lane];
        acc.x += v.x; acc.y += v.y; acc.z += v.z; acc.w += v.w;
    }
    int d = e - b;
    float inv = 1.0f / (float)(d > 0 ? d : 1);
    acc.x *= inv; acc.y *= inv; acc.z *= inv; acc.w *= inv;
    ((float4*)(mean + (size_t)w * D128))[lane] = acc;
}

__global__ void k_aggregate(const float* __restrict__ X, const int* __restrict__ rowptr,
                            const int* __restrict__ nbr, const int* __restrict__ c2o,
                            const int* __restrict__ o2c, float* __restrict__ mean, int n) {
    int w = (blockIdx.x * blockDim.x + threadIdx.x) >> 5;
    int lane = threadIdx.x & 31;
    if (w >= n) return;
    int o = c2o[w];
    int b = rowptr[o], e = rowptr[o + 1];
    float4 acc = make_float4(0.f, 0.f, 0.f, 0.f);
    float cnt = 0.f;
#pragma unroll 4
    for (int j = b; j < e; j++) {
        int c = o2c[nbr[j]];
        float wgt = (c >= 0) ? 1.f : 0.f;
        int idx = (c >= 0) ? c : 0;
        float4 v = ((const float4*)(X + (size_t)idx * D128))[lane];
        acc.x += wgt * v.x; acc.y += wgt * v.y;
        acc.z += wgt * v.z; acc.w += wgt * v.w;
        cnt += wgt;
    }
    float inv = 1.0f / fmaxf(cnt, 1.f);
    acc.x *= inv; acc.y *= inv; acc.z *= inv; acc.w *= inv;
    ((float4*)(mean + (size_t)w * D128))[lane] = acc;
}

// ---------------- tf32 mma GEMM, double-buffered, M=128 tile (frozen) ----------------
#define ACH 16
#define ASTR 20
#define BSTR 136
#define OF_AH 0
#define OF_AL (128 * ASTR)
#define OF_BH (2 * 128 * ASTR)
#define OF_BL (2 * 128 * ASTR + ACH * BSTR)
#define PBUF  (2 * 128 * ASTR + 2 * ACH * BSTR)
#define GEMM_SMEM_BYTES (2 * PBUF * 4)

__global__ void __launch_bounds__(256, 2)
k_gemm_mma(const float* __restrict__ Am, const float* __restrict__ Ax,
           const float* __restrict__ Bhi, const float* __restrict__ Blo,
           const float* __restrict__ bias, const float* __restrict__ pw,
           float* __restrict__ H, float* __restrict__ score, int n) {
    extern __shared__ float smem[];
    __shared__ float s_rnorm;
    int t = threadIdx.x, lane = t & 31, wid = t >> 5;
    int wm = (wid >> 2) * 64;
    int wn = (wid & 3) * 32;
    int m0 = blockIdx.x * 128;

    if (t < 32) {
        float4 w4 = ((const float4*)pw)[t];
        float nn = w4.x * w4.x + w4.y * w4.y + w4.z * w4.z + w4.w * w4.w;
#pragma unroll
        for (int off = 16; off > 0; off >>= 1)
            nn += __shfl_xor_sync(0xFFFFFFFF, nn, off);
        if (t == 0) s_rnorm = 1.0f / sqrtf(nn);
    }

    float c[4][4][4];
#pragma unroll
    for (int i = 0; i < 4; i++)
#pragma unroll
        for (int j = 0; j < 4; j++)
#pragma unroll
            for (int r = 0; r < 4; r++) c[i][j][r] = 0.f;

    int arow = t >> 1, acol0 = (t & 1) * 8;
    int brow = t >> 4, bcol0 = (t & 15) * 8;

    float4 sa0, sa1, sbh0, sbh1, sbl0, sbl1;
    {
        const float* A = Am + (size_t)(m0 + arow) * D128 + acol0;
        sa0 = *(const float4*)A;
        sa1 = *(const float4*)(A + 4);
        const float* bhp = Bhi + (size_t)brow * D128 + bcol0;
        const float* blp = Blo + (size_t)brow * D128 + bcol0;
        sbh0 = *(const float4*)bhp;  sbh1 = *(const float4*)(bhp + 4);
        sbl0 = *(const float4*)blp;  sbl1 = *(const float4*)(blp + 4);
    }
    {
        float* buf = smem;
        float4 hv, lv;
        float* ah = buf + OF_AH + arow * ASTR + acol0;
        float* al = buf + OF_AL + arow * ASTR + acol0;
        split4(sa0, hv, lv);
        *(float4*)ah = hv; *(float4*)al = lv;
        split4(sa1, hv, lv);
        *(float4*)(ah + 4) = hv; *(float4*)(al + 4) = lv;
        float* bh = buf + OF_BH + brow * BSTR + bcol0;
        float* bl = buf + OF_BL + brow * BSTR + bcol0;
        *(float4*)bh = sbh0; *(float4*)(bh + 4) = sbh1;
        *(float4*)bl = sbl0; *(float4*)(bl + 4) = sbl1;
    }

    for (int ch = 0; ch < 16; ch++) {
        __syncthreads();
        if (ch < 15) {
            int nc = ch + 1;
            const float* A = (nc < 8)
                ? Am + (size_t)(m0 + arow) * D128 + nc * ACH + acol0
                : Ax + (size_t)(m0 + arow) * D128 + (nc - 8) * ACH + acol0;
            sa0 = *(const float4*)A;
            sa1 = *(const float4*)(A + 4);
            const float* bhp = Bhi + (size_t)(nc * ACH + brow) * D128 + bcol0;
            const float* blp = Blo + (size_t)(nc * ACH + brow) * D128 + bcol0;
            sbh0 = *(const float4*)bhp;  sbh1 = *(const float4*)(bhp + 4);
            sbl0 = *(const float4*)blp;  sbl1 = *(const float4*)(blp + 4);
        }
        const float* Ahb = smem + (ch & 1) * PBUF + OF_AH;
        const float* Alb = smem + (ch & 1) * PBUF + OF_AL;
        const float* Bhb = smem + (ch & 1) * PBUF + OF_BH;
        const float* Blb = smem + (ch & 1) * PBUF + OF_BL;
#pragma unroll
        for (int ks = 0; ks < 2; ks++) {
            uint32_t ah[4][4], bh[4][2];
#pragma unroll
            for (int mf = 0; mf < 4; mf++)
#pragma unroll
                for (int r = 0; r < 4; r++)
                    ah[mf][r] = __float_as_uint(
                        Ahb[(wm + mf * 16 + (lane >> 2) + 8 * (r & 1)) * ASTR
                            + ks * 8 + (lane & 3) + 4 * (r >> 1)]);
#pragma unroll
            for (int nf = 0; nf < 4; nf++)
#pragma unroll
                for (int r = 0; r < 2; r++)
                    bh[nf][r] = __float_as_uint(
                        Bhb[(ks * 8 + (lane & 3) + 4 * r) * BSTR + wn + nf * 8 + (lane >> 2)]);
#pragma unroll
            for (int mf = 0; mf < 4; mf++)
#pragma unroll
                for (int nf = 0; nf < 4; nf++)
                    mma_m16n8k8(c[mf][nf], ah[mf], bh[nf]);
            {
                uint32_t blo[4][2];
#pragma unroll
                for (int nf = 0; nf < 4; nf++)
#pragma unroll
                    for (int r = 0; r < 2; r++)
                        blo[nf][r] = __float_as_uint(
                            Blb[(ks * 8 + (lane & 3) + 4 * r) * BSTR + wn + nf * 8 + (lane >> 2)]);
#pragma unroll
                for (int mf = 0; mf < 4; mf++)
#pragma unroll
                    for (int nf = 0; nf < 4; nf++)
                        mma_m16n8k8(c[mf][nf], ah[mf], blo[nf]);
            }
            {
                uint32_t al[4][4];
#pragma unroll
                for (int mf = 0; mf < 4; mf++)
#pragma unroll
                    for (int r = 0; r < 4; r++)
                        al[mf][r] = __float_as_uint(
                            Alb[(wm + mf * 16 + (lane >> 2) + 8 * (r & 1)) * ASTR
                                + ks * 8 + (lane & 3) + 4 * (r >> 1)]);
#pragma unroll
                for (int mf = 0; mf < 4; mf++)
#pragma unroll
                    for (int nf = 0; nf < 4; nf++)
                        mma_m16n8k8(c[mf][nf], al[mf], bh[nf]);
            }
        }
        if (ch < 15) {
            float* buf = smem + ((ch + 1) & 1) * PBUF;
            float4 hv, lv;
            float* ah = buf + OF_AH + arow * ASTR + acol0;
            float* al = buf + OF_AL + arow * ASTR + acol0;
            split4(sa0, hv, lv);
            *(float4*)ah = hv; *(float4*)al = lv;
            split4(sa1, hv, lv);
            *(float4*)(ah + 4) = hv; *(float4*)(al + 4) = lv;
            float* bh = buf + OF_BH + brow * BSTR + bcol0;
            float* bl = buf + OF_BL + brow * BSTR + bcol0;
            *(float4*)bh = sbh0; *(float4*)(bh + 4) = sbh1;
            *(float4*)bl = sbl0; *(float4*)(bl + 4) = sbl1;
        }
    }

    int r0 = lane >> 2, cq = (lane & 3) * 2;
    float pwv[4][2];
#pragma unroll
    for (int nf = 0; nf < 4; nf++) {
        pwv[nf][0] = pw[wn + nf * 8 + cq];
        pwv[nf][1] = pw[wn + nf * 8 + cq + 1];
    }
    float* sdot = smem + OF_BH;
#pragma unroll
    for (int mf = 0; mf < 4; mf++) {
        int row = m0 + wm + mf * 16 + r0;
        float p0 = 0.f, p1 = 0.f;
#pragma unroll
        for (int nf = 0; nf < 4; nf++) {
            int col = wn + nf * 8 + cq;
            float b0 = bias[col], b1 = bias[col + 1];
            float2 o0, o1;
            o0.x = fmaxf(c[mf][nf][0] + b0, 0.f);
            o0.y = fmaxf(c[mf][nf][1] + b1, 0.f);
            o1.x = fmaxf(c[mf][nf][2] + b0, 0.f);
            o1.y = fmaxf(c[mf][nf][3] + b1, 0.f);
            *(float2*)(H + (size_t)row * D128 + col) = o0;
            *(float2*)(H + (size_t)(row + 8) * D128 + col) = o1;
            p0 += o0.x * pwv[nf][0] + o0.y * pwv[nf][1];
            p1 += o1.x * pwv[nf][0] + o1.y * pwv[nf][1];
        }
        p0 += __shfl_xor_sync(0xFFFFFFFF, p0, 1);
        p0 += __shfl_xor_sync(0xFFFFFFFF, p0, 2);
        p1 += __shfl_xor_sync(0xFFFFFFFF, p1, 1);
        p1 += __shfl_xor_sync(0xFFFFFFFF, p1, 2);
        if ((lane & 3) == 0) {
            int rr = wm + mf * 16 + r0;
            sdot[rr * 4 + (wid & 3)] = p0;
            sdot[(rr + 8) * 4 + (wid & 3)] = p1;
        }
    }
    __syncthreads();
    if (t < 128) {
        float4 d4 = *(float4*)&sdot[t * 4];
        float dot = d4.x + d4.y + d4.z + d4.w;
        score[m0 + t] = tanhf(dot * s_rnorm);
    }
}

// ---------------- tf32 mma GEMM, double-buffered, M=64 tile (frozen) ----------------
#define OF64_AH 0
#define OF64_AL (64 * ASTR)
#define OF64_BH (2 * 64 * ASTR)
#define OF64_BL (2 * 64 * ASTR + ACH * BSTR)
#define PBUF64  (2 * 64 * ASTR + 2 * ACH * BSTR)
#define GEMM64_SMEM_BYTES (2 * PBUF64 * 4)

__global__ void __launch_bounds__(256, 2)
k_gemm_mma64(const float* __restrict__ Am, const float* __restrict__ Ax,
             const float* __restrict__ Bhi, const float* __restrict__ Blo,
             const float* __restrict__ bias, const float* __restrict__ pw,
             float* __restrict__ H, float* __restrict__ score, int n) {
    extern __shared__ float smem[];
    __shared__ float s_rnorm;
    int t = threadIdx.x, lane = t & 31, wid = t >> 5;
    int wm = (wid >> 2) * 32;
    int wn = (wid & 3) * 32;
    int m0 = blockIdx.x * 64;

    if (t < 32) {
        float4 w4 = ((const float4*)pw)[t];
        float nn = w4.x * w4.x + w4.y * w4.y + w4.z * w4.z + w4.w * w4.w;
#pragma unroll
        for (int off = 16; off > 0; off >>= 1)
            nn += __shfl_xor_sync(0xFFFFFFFF, nn, off);
        if (t == 0) s_rnorm = 1.0f / sqrtf(nn);
    }

    float c[2][4][4];
#pragma unroll
    for (int i = 0; i < 2; i++)
#pragma unroll
        for (int j = 0; j < 4; j++)
#pragma unroll
            for (int r = 0; r < 4; r++) c[i][j][r] = 0.f;

    int arow = t >> 2, acol0 = (t & 3) * 4;
    int brow = t >> 4, bcol0 = (t & 15) * 8;

    float4 sa0, sbh0, sbh1, sbl0, sbl1;
    {
        sa0 = *(const float4*)(Am + (size_t)(m0 + arow) * D128 + acol0);
        const float* bhp = Bhi + (size_t)brow * D128 + bcol0;
        const float* blp = Blo + (size_t)brow * D128 + bcol0;
        sbh0 = *(const float4*)bhp;  sbh1 = *(const float4*)(bhp + 4);
        sbl0 = *(const float4*)blp;  sbl1 = *(const float4*)(blp + 4);
    }
    {
        float* buf = smem;
        float4 hv, lv;
        split4(sa0, hv, lv);
        *(float4*)(buf + OF64_AH + arow * ASTR + acol0) = hv;
        *(float4*)(buf + OF64_AL + arow * ASTR + acol0) = lv;
        float* bh = buf + OF64_BH + brow * BSTR + bcol0;
        float* bl = buf + OF64_BL + brow * BSTR + bcol0;
        *(float4*)bh = sbh0; *(float4*)(bh + 4) = sbh1;
        *(float4*)bl = sbl0; *(float4*)(bl + 4) = sbl1;
    }

    for (int ch = 0; ch < 16; ch++) {
        __syncthreads();
        if (ch < 15) {
            int nc = ch + 1;
            const float* A = (nc < 8)
                ? Am + (size_t)(m0 + arow) * D128 + nc * ACH + acol0
                : Ax + (size_t)(m0 + arow) * D128 + (nc - 8) * ACH + acol0;
            sa0 = *(const float4*)A;
            const float* bhp = Bhi + (size_t)(nc * ACH + brow) * D128 + bcol0;
            const float* blp = Blo + (size_t)(nc * ACH + brow) * D128 + bcol0;
            sbh0 = *(const float4*)bhp;  sbh1 = *(const float4*)(bhp + 4);
            sbl0 = *(const float4*)blp;  sbl1 = *(const float4*)(blp + 4);
        }
        const float* Ahb = smem + (ch & 1) * PBUF64 + OF64_AH;
        const float* Alb = smem + (ch & 1) * PBUF64 + OF64_AL;
        const float* Bhb = smem + (ch & 1) * PBUF64 + OF64_BH;
        const float* Blb = smem + (ch & 1) * PBUF64 + OF64_BL;
#pragma unroll
        for (int ks = 0; ks < 2; ks++) {
            uint32_t ah[2][4], bh[4][2];
#pragma unroll
            for (int mf = 0; mf < 2; mf++)
#pragma unroll
                for (int r = 0; r < 4; r++)
                    ah[mf][r] = __float_as_uint(
                        Ahb[(wm + mf * 16 + (lane >> 2) + 8 * (r & 1)) * ASTR
                            + ks * 8 + (lane & 3) + 4 * (r >> 1)]);
#pragma unroll
            for (int nf = 0; nf < 4; nf++)
#pragma unroll
                for (int r = 0; r < 2; r++)
                    bh[nf][r] = __float_as_uint(
                        Bhb[(ks * 8 + (lane & 3) + 4 * r) * BSTR + wn + nf * 8 + (lane >> 2)]);
#pragma unroll
            for (int mf = 0; mf < 2; mf++)
#pragma unroll
                for (int nf = 0; nf < 4; nf++)
                    mma_m16n8k8(c[mf][nf], ah[mf], bh[nf]);
            {
                uint32_t blo[4][2];
#pragma unroll
                for (int nf = 0; nf < 4; nf++)
#pragma unroll
                    for (int r = 0; r < 2; r++)
                        blo[nf][r] = __float_as_uint(
                            Blb[(ks * 8 + (lane & 3) + 4 * r) * BSTR + wn + nf * 8 + (lane >> 2)]);
#pragma unroll
                for (int mf = 0; mf < 2; mf++)
#pragma unroll
                    for (int nf = 0; nf < 4; nf++)
                        mma_m16n8k8(c[mf][nf], ah[mf], blo[nf]);
            }
            {
                uint32_t al[2][4];
#pragma unroll
                for (int mf = 0; mf < 2; mf++)
#pragma unroll
                    for (int r = 0; r < 4; r++)
                        al[mf][r] = __float_as_uint(
                            Alb[(wm + mf * 16 + (lane >> 2) + 8 * (r & 1)) * ASTR
                                + ks * 8 + (lane & 3) + 4 * (r >> 1)]);
#pragma unroll
                for (int mf = 0; mf < 2; mf++)
#pragma unroll
                    for (int nf = 0; nf < 4; nf++)
                        mma_m16n8k8(c[mf][nf], al[mf], bh[nf]);
            }
        }
        if (ch < 15) {
            float* buf = smem + ((ch + 1) & 1) * PBUF64;
            float4 hv, lv;
            split4(sa0, hv, lv);
            *(float4*)(buf + OF64_AH + arow * ASTR + acol0) = hv;
            *(float4*)(buf + OF64_AL + arow * ASTR + acol0) = lv;
            float* bh = buf + OF64_BH + brow * BSTR + bcol0;
            float* bl = buf + OF64_BL + brow * BSTR + bcol0;
            *(float4*)bh = sbh0; *(float4*)(bh + 4) = sbh1;
            *(float4*)bl = sbl0; *(float4*)(bl + 4) = sbl1;
        }
    }

    int r0 = lane >> 2, cq = (lane & 3) * 2;
    float pwv[4][2];
#pragma unroll
    for (int nf = 0; nf < 4; nf++) {
        pwv[nf][0] = pw[wn + nf * 8 + cq];
        pwv[nf][1] = pw[wn + nf * 8 + cq + 1];
    }
    float* sdot = smem + OF64_BH;
#pragma unroll
    for (int mf = 0; mf < 2; mf++) {
        int row = m0 + wm + mf * 16 + r0;
        float p0 = 0.f, p1 = 0.f;
#pragma unroll
        for (int nf = 0; nf < 4; nf++) {
            int col = wn + nf * 8 + cq;
            float b0 = bias[col], b1 = bias[col + 1];
            float2 o0, o1;
            o0.x = fmaxf(c[mf][nf][0] + b0, 0.f);
            o0.y = fmaxf(c[mf][nf][1] + b1, 0.f);
            o1.x = fmaxf(c[mf][nf][2] + b0, 0.f);
            o1.y = fmaxf(c[mf][nf][3] + b1, 0.f);
            *(float2*)(H + (size_t)row * D128 + col) = o0;
            *(float2*)(H + (size_t)(row + 8) * D128 + col) = o1;
            p0 += o0.x * pwv[nf][0] + o0.y * pwv[nf][1];
            p1 += o1.x * pwv[nf][0] + o1.y * pwv[nf][1];
        }
        p0 += __shfl_xor_sync(0xFFFFFFFF, p0, 1);
        p0 += __shfl_xor_sync(0xFFFFFFFF, p0, 2);
        p1 += __shfl_xor_sync(0xFFFFFFFF, p1, 1);
        p1 += __shfl_xor_sync(0xFFFFFFFF, p1, 2);
        if ((lane & 3) == 0) {
            int rr = wm + mf * 16 + r0;
            sdot[rr * 4 + (wid & 3)] = p0;
            sdot[(rr + 8) * 4 + (wid & 3)] = p1;
        }
    }
    __syncthreads();
    if (t < 64) {
        float4 d4 = *(float4*)&sdot[t * 4];
        float dot = d4.x + d4.y + d4.z + d4.w;
        score[m0 + t] = tanhf(dot * s_rnorm);
    }
}

// ---------------- top-K: packed-u64 hybrid bitonic + pool/readout/compose (+ fused MLP) ----------------
__global__ void k_topk(const float* __restrict__ score, const float* __restrict__ H,
                       float* __restrict__ pool, int* __restrict__ newid,
                       float* __restrict__ s_out, int* __restrict__ o2c,
                       int* __restrict__ c2o, int Npg, int K, int round, int do_compose,
                       const float* __restrict__ W1, const float* __restrict__ b1,
                       const float* __restrict__ W2, const float* __restrict__ b2,
                       const float* __restrict__ W3, const float* __restrict__ b3,
                       float* __restrict__ out, int do_mlp) {
    __shared__ unsigned long long sp[1024];
    __shared__ float rmx[8][128];
    __shared__ float rsm[8][128];
    __shared__ float mlp_sh[256];
    __shared__ float mlp_h1[128];
    __shared__ float mlp_h2[64];
    __shared__ float mlp_red[128];
    int g = blockIdx.x;
    int t = threadIdx.x;   // 1024 threads

    float key = (t < Npg) ? score[g * Npg + t] : -INFINITY;
    uint32_t u = __float_as_uint(key);
    uint32_t ou = (u & 0x80000000u) ? ~u : (u | 0x80000000u);
    unsigned long long p = ((unsigned long long)ou << 32) | (unsigned)t;

    // rounds k=2..32: intra-warp, register + shfl
#pragma unroll
    for (int k = 2; k <= 32; k <<= 1) {
#pragma unroll
        for (int j = k >> 1; j > 0; j >>= 1) {
            unsigned long long op = __shfl_xor_sync(0xFFFFFFFF, p, j);
            bool up = ((t & j) == 0);
            bool desc = ((t & k) == 0);
            bool keep_max = (up == desc);
            if (keep_max ? (op > p) : (op < p)) p = op;
        }
    }
    // rounds k=64..1024: j>=32 phases in smem (u64 moves), j<=16 in registers
    for (int k = 64; k <= 1024; k <<= 1) {
        sp[t] = p;
        __syncthreads();
        for (int j = k >> 1; j >= 32; j >>= 1) {
            int ixj = t ^ j;
            if (ixj > t) {
                bool desc = ((t & k) == 0);
                unsigned long long a = sp[t], b = sp[ixj];
                bool sw = desc ? (a < b) : (a > b);
                if (sw) { sp[t] = b; sp[ixj] = a; }
            }
            __syncthreads();
        }
        p = sp[t];
#pragma unroll
        for (int j = 16; j > 0; j >>= 1) {
            unsigned long long op = __shfl_xor_sync(0xFFFFFFFF, p, j);
            bool up = ((t & j) == 0);
            bool desc = ((t & k) == 0);
            bool keep_max = (up == desc);
            if (keep_max ? (op > p) : (op < p)) p = op;
        }
    }
    sp[t] = p;
    __syncthreads();

    if (t < Npg) {
        int node = (int)(sp[t] & 0xFFFFFFFFu);
        newid[g * Npg + node] = (t < K) ? (g * K + t) : -1;
    }
    __syncthreads();
    if (do_compose) {
        int o = g * NPG0 + t;
        int c = o2c[o];
        int nc = (c >= 0) ? newid[c] : -1;
        o2c[o] = nc;
        if (nc >= 0) c2o[nc] = o;
    }
    int f = t & 127, part = t >> 7;
    float mx = -INFINITY, sm = 0.f;
    for (int r = part; r < K; r += 8) {
        unsigned long long q = sp[r];
        int node = (int)(q & 0xFFFFFFFFu);
        uint32_t oku = (uint32_t)(q >> 32);
        uint32_t ku = (oku & 0x80000000u) ? (oku & 0x7FFFFFFFu) : ~oku;
        float kr = __uint_as_float(ku);
        float v = H[(size_t)(g * Npg + node) * D128 + f] * kr;
        pool[(size_t)(g * K + r) * D128 + f] = v;
        mx = fmaxf(mx, v);
        sm += v;
    }
    rmx[part][f] = mx; rsm[part][f] = sm;
    __syncthreads();
    if (t < 128) {
        float m2 = rmx[0][f], s2 = rsm[0][f];
#pragma unroll
        for (int pp = 1; pp < 8; pp++) {
            m2 = fmaxf(m2, rmx[pp][f]);
            s2 += rsm[pp][f];
        }
        float mean = s2 / (float)K;
        if (round == 0) {
            s_out[g * 256 + f] = m2;
            s_out[g * 256 + 128 + f] = mean;
        } else {
            s_out[g * 256 + f] += m2;
            s_out[g * 256 + 128 + f] += mean;
        }
    }

    // ---- fused final MLP (round 2 only): 256->128->64->1 + sigmoid ----
    if (do_mlp) {
        __syncthreads();
        if (t < 128) {
            mlp_sh[t] = s_out[g * 256 + t];
            mlp_sh[t + 128] = s_out[g * 256 + 128 + t];
        }
        __syncthreads();
        if (t < 128) {
            float acc = b1[t];
            for (int k = 0; k < 256; k++) acc += mlp_sh[k] * W1[k * 128 + t];
            mlp_h1[t] = fmaxf(acc, 0.f);
        }
        __syncthreads();
        if (t < 64) {
            float a = b2[t];
            for (int k = 0; k < 128; k++) a += mlp_h1[k] * W2[k * 64 + t];
            mlp_h2[t] = fmaxf(a, 0.f);
        }
        __syncthreads();
        if (t < 128) mlp_red[t] = (t < 64) ? mlp_h2[t] * W3[t] : 0.f;
        __syncthreads();
        for (int off = 64; off > 0; off >>= 1) {
            if (t < off) mlp_red[t] += mlp_red[t + off];
            __syncthreads();
        }
        if (t == 0) out[g] = 1.f / (1.f + expf(-(mlp_red[0] + b3[0])));
    }
}

// ---------------- host orchestration ----------------
extern "C" void kernel_launch(void* const* d_in, const int* in_sizes, int n_in,
                              void* d_out, int out_size) {
    const float* x   = (const float*)d_in[0];
    const int*   ei  = (const int*)d_in[1];
    const int E = in_sizes[1] / 2;
    const int epg = E / BGR;

    const float* Wl1 = (const float*)d_in[2];
    const float* bl1 = (const float*)d_in[3];
    const float* Wr1 = (const float*)d_in[4];
    const float* pw1 = (const float*)d_in[5];
    const float* Wl2 = (const float*)d_in[6];
    const float* bl2 = (const float*)d_in[7];
    const float* Wr2 = (const float*)d_in[8];
    const float* pw2 = (const float*)d_in[9];
    const float* Wl3 = (const float*)d_in[10];
    const float* bl3 = (const float*)d_in[11];
    const float* Wr3 = (const float*)d_in[12];
    const float* pw3 = (const float*)d_in[13];
    const float* W1  = (const float*)d_in[14];
    const float* b1  = (const float*)d_in[15];
    const float* W2  = (const float*)d_in[16];
    const float* b2  = (const float*)d_in[17];
    const float* W3  = (const float*)d_in[18];
    const float* b3  = (const float*)d_in[19];

    float *meanP, *hP, *poolA, *poolB, *scoreP, *sP, *bhiP, *bloP;
    int *newidP, *o2cP, *c2oP, *rpP, *nbrP;
    cudaGetSymbolAddress((void**)&meanP, g_mean);
    cudaGetSymbolAddress((void**)&hP, g_h);
    cudaGetSymbolAddress((void**)&poolA, g_poolA);
    cudaGetSymbolAddress((void**)&poolB, g_poolB);
    cudaGetSymbolAddress((void**)&scoreP, g_score);
    cudaGetSymbolAddress((void**)&sP, g_s);
    cudaGetSymbolAddress((void**)&bhiP, g_bhi);
    cudaGetSymbolAddress((void**)&bloP, g_blo);
    cudaGetSymbolAddress((void**)&newidP, g_newid);
    cudaGetSymbolAddress((void**)&o2cP, g_orig2cur);
    cudaGetSymbolAddress((void**)&c2oP, g_cur2orig);
    cudaGetSymbolAddress((void**)&rpP, g_rowptr);
    cudaGetSymbolAddress((void**)&nbrP, g_nbr);

    cudaFuncSetAttribute(k_gemm_mma, cudaFuncAttributeMaxDynamicSharedMemorySize,
                         GEMM_SMEM_BYTES);
    cudaFuncSetAttribute(k_gemm_mma64, cudaFuncAttributeMaxDynamicSharedMemorySize,
                         GEMM64_SMEM_BYTES);

    const int TB = 256;

    // one-time: CSR + map init + weight split in a single launch
    k_init<<<BGR + 96, 1024>>>(ei, ei + E, epg, rpP, nbrP, o2cP, c2oP,
                               Wl1, Wr1, Wl2, Wr2, Wl3, Wr3, bhiP, bloP);

    struct LayerCfg {
        const float *xin, *bl, *pw;
        float* pool;
        int n, Npg, K, round;
    };
    LayerCfg layers[3] = {
        { x,     bl1, pw1, poolA, BGR * NPG0, NPG0, K1, 0 },
        { poolA, bl2, pw2, poolB, BGR * K1,   K1,   K2, 1 },
        { poolB, bl3, pw3, poolA, BGR * K2,   K2,   K3, 2 },
    };

    for (int L = 0; L < 3; L++) {
        LayerCfg& c = layers[L];
        int n = c.n;
        if (L == 0)
            k_aggregate1<<<(n * 32 + TB - 1) / TB, TB>>>(c.xin, rpP, nbrP, meanP, n);
        else
            k_aggregate<<<(n * 32 + TB - 1) / TB, TB>>>(c.xin, rpP, nbrP, c2oP, o2cP, meanP, n);
        if (L == 0)
            k_gemm_mma<<<n / 128, 256, GEMM_SMEM_BYTES>>>(
                meanP, c.xin, bhiP + L * 256 * D128, bloP + L * 256 * D128,
                c.bl, c.pw, hP, scoreP, n);
        else
            k_gemm_mma64<<<n / 64, 256, GEMM64_SMEM_BYTES>>>(
                meanP, c.xin, bhiP + L * 256 * D128, bloP + L * 256 * D128,
                c.bl, c.pw, hP, scoreP, n);
        k_topk<<<BGR, 1024>>>(scoreP, hP, c.pool, newidP, sP, o2cP, c2oP,
                              c.Npg, c.K, c.round, (L < 2) ? 1 : 0,
                              W1, b1, W2, b2, W3, b3, (float*)d_out,
                              (L == 2) ? 1 : 0);
    }
}

// round 16
// speedup vs baseline: 1.0356x; 1.0356x over previous
#include <cuda_runtime.h>
#include <math.h>
#include <stdint.h>

// ---------------- problem constants ----------------
#define D128 128
#define BGR 64
#define NPG0 1024
#define NMAX (BGR * NPG0)        // 65536
#define EMAX 1048576
#define K1 820
#define K2 656
#define K3 525

// ---------------- scratch ----------------
__device__ float g_mean[NMAX * D128];
__device__ float g_h[NMAX * D128];
__device__ float g_poolA[BGR * K1 * D128];
__device__ float g_poolB[BGR * K2 * D128];
__device__ float g_score[NMAX];
__device__ int   g_newid[NMAX];
__device__ int   g_orig2cur[NMAX];
__device__ int   g_cur2orig[NMAX];
__device__ int   g_rowptr[NMAX + 1];
__device__ int   g_nbr[EMAX];
__device__ float g_bhi[3][256 * D128];
__device__ float g_blo[3][256 * D128];
__device__ float g_s[BGR * 256];

__device__ __forceinline__ void tf32_split(float v, uint32_t& hi, uint32_t& lo) {
    asm("cvt.rna.tf32.f32 %0, %1;" : "=r"(hi) : "f"(v));
    float r = v - __uint_as_float(hi);
    asm("cvt.rna.tf32.f32 %0, %1;" : "=r"(lo) : "f"(r));
}

__device__ __forceinline__ void mma_m16n8k8(float* c, const uint32_t* a, const uint32_t* b) {
    asm volatile(
        "mma.sync.aligned.m16n8k8.row.col.f32.tf32.tf32.f32 "
        "{%0,%1,%2,%3}, {%4,%5,%6,%7}, {%8,%9}, {%0,%1,%2,%3};"
        : "+f"(c[0]), "+f"(c[1]), "+f"(c[2]), "+f"(c[3])
        : "r"(a[0]), "r"(a[1]), "r"(a[2]), "r"(a[3]), "r"(b[0]), "r"(b[1]));
}

__device__ __forceinline__ void split4(float4 v, float4& hv, float4& lv) {
    uint32_t h0, h1, h2, h3, l0, l1, l2, l3;
    tf32_split(v.x, h0, l0); tf32_split(v.y, h1, l1);
    tf32_split(v.z, h2, l2); tf32_split(v.w, h3, l3);
    hv = make_float4(__uint_as_float(h0), __uint_as_float(h1),
                     __uint_as_float(h2), __uint_as_float(h3));
    lv = make_float4(__uint_as_float(l0), __uint_as_float(l1),
                     __uint_as_float(l2), __uint_as_float(l3));
}

// ---------------- init: CSR (blocks 0..63) + weight split (blocks 64..159) ----------------
__global__ void __launch_bounds__(1024)
k_init(const int* __restrict__ src, const int* __restrict__ dst, int epg,
       int* __restrict__ rowptr, int* __restrict__ nbr,
       int* __restrict__ o2c, int* __restrict__ c2o,
       const float* __restrict__ Wl1, const float* __restrict__ Wr1,
       const float* __restrict__ Wl2, const float* __restrict__ Wr2,
       const float* __restrict__ Wl3, const float* __restrict__ Wr3,
       float* __restrict__ bh, float* __restrict__ bl) {
    __shared__ int deg[1024];
    __shared__ int cur[1024];
    int t = threadIdx.x;
    if (blockIdx.x >= BGR) {
        int i = (blockIdx.x - BGR) * 1024 + t;   // 0..98303
        int l = i >> 15, j = i & 32767;
        const float* Wl = (l == 0) ? Wl1 : (l == 1) ? Wl2 : Wl3;
        const float* Wr = (l == 0) ? Wr1 : (l == 1) ? Wr2 : Wr3;
        float v = (j < 16384) ? Wl[j] : Wr[j - 16384];
        uint32_t hi, lo;
        tf32_split(v, hi, lo);
        bh[i] = __uint_as_float(hi);
        bl[i] = __uint_as_float(lo);
        return;
    }
    int g = blockIdx.x;
    int ebase = g * epg;
    int nbase = g * NPG0;

    deg[t] = 0;
    __syncthreads();
    for (int e = ebase + t; e < ebase + epg; e += 1024)
        atomicAdd(&deg[dst[e] - nbase], 1);
    __syncthreads();
    int my = deg[t];
    cur[t] = my;
    __syncthreads();
    for (int off = 1; off < 1024; off <<= 1) {
        int v = cur[t];
        if (t >= off) v += cur[t - off];
        __syncthreads();
        cur[t] = v;
        __syncthreads();
    }
    int ex = cur[t] - my;
    rowptr[nbase + t] = ebase + ex;
    o2c[nbase + t] = nbase + t;
    c2o[nbase + t] = nbase + t;
    if (g == 0 && t == 0) rowptr[NMAX] = BGR * epg;
    __syncthreads();
    cur[t] = ex;
    __syncthreads();
    for (int e = ebase + t; e < ebase + epg; e += 1024) {
        int d = dst[e] - nbase;
        int p = atomicAdd(&cur[d], 1);
        nbr[ebase + p] = src[e];
    }
}

// ---------------- mean aggregation ----------------
__global__ void k_aggregate1(const float* __restrict__ X, const int* __restrict__ rowptr,
                             const int* __restrict__ nbr, float* __restrict__ mean, int n) {
    int w = (blockIdx.x * blockDim.x + threadIdx.x) >> 5;
    int lane = threadIdx.x & 31;
    if (w >= n) return;
    int b = rowptr[w], e = rowptr[w + 1];
    float4 acc = make_float4(0.f, 0.f, 0.f, 0.f);
#pragma unroll 4
    for (int j = b; j < e; j++) {
        float4 v = ((const float4*)(X + (size_t)nbr[j] * D128))[lane];
        acc.x += v.x; acc.y += v.y; acc.z += v.z; acc.w += v.w;
    }
    int d = e - b;
    float inv = 1.0f / (float)(d > 0 ? d : 1);
    acc.x *= inv; acc.y *= inv; acc.z *= inv; acc.w *= inv;
    ((float4*)(mean + (size_t)w * D128))[lane] = acc;
}

__global__ void k_aggregate(const float* __restrict__ X, const int* __restrict__ rowptr,
                            const int* __restrict__ nbr, const int* __restrict__ c2o,
                            const int* __restrict__ o2c, float* __restrict__ mean, int n) {
    int w = (blockIdx.x * blockDim.x + threadIdx.x) >> 5;
    int lane = threadIdx.x & 31;
    if (w >= n) return;
    int o = c2o[w];
    int b = rowptr[o], e = rowptr[o + 1];
    float4 acc = make_float4(0.f, 0.f, 0.f, 0.f);
    float cnt = 0.f;
#pragma unroll 4
    for (int j = b; j < e; j++) {
        int c = o2c[nbr[j]];
        float wgt = (c >= 0) ? 1.f : 0.f;
        int idx = (c >= 0) ? c : 0;
        float4 v = ((const float4*)(X + (size_t)idx * D128))[lane];
        acc.x += wgt * v.x; acc.y += wgt * v.y;
        acc.z += wgt * v.z; acc.w += wgt * v.w;
        cnt += wgt;
    }
    float inv = 1.0f / fmaxf(cnt, 1.f);
    acc.x *= inv; acc.y *= inv; acc.z *= inv; acc.w *= inv;
    ((float4*)(mean + (size_t)w * D128))[lane] = acc;
}

// ---------------- tf32 mma GEMM, double-buffered, M=128 tile (frozen) ----------------
#define ACH 16
#define ASTR 20
#define BSTR 136
#define OF_AH 0
#define OF_AL (128 * ASTR)
#define OF_BH (2 * 128 * ASTR)
#define OF_BL (2 * 128 * ASTR + ACH * BSTR)
#define PBUF  (2 * 128 * ASTR + 2 * ACH * BSTR)
#define GEMM_SMEM_BYTES (2 * PBUF * 4)

__global__ void __launch_bounds__(256, 2)
k_gemm_mma(const float* __restrict__ Am, const float* __restrict__ Ax,
           const float* __restrict__ Bhi, const float* __restrict__ Blo,
           const float* __restrict__ bias, const float* __restrict__ pw,
           float* __restrict__ H, float* __restrict__ score, int n) {
    extern __shared__ float smem[];
    __shared__ float s_rnorm;
    int t = threadIdx.x, lane = t & 31, wid = t >> 5;
    int wm = (wid >> 2) * 64;
    int wn = (wid & 3) * 32;
    int m0 = blockIdx.x * 128;

    if (t < 32) {
        float4 w4 = ((const float4*)pw)[t];
        float nn = w4.x * w4.x + w4.y * w4.y + w4.z * w4.z + w4.w * w4.w;
#pragma unroll
        for (int off = 16; off > 0; off >>= 1)
            nn += __shfl_xor_sync(0xFFFFFFFF, nn, off);
        if (t == 0) s_rnorm = 1.0f / sqrtf(nn);
    }

    float c[4][4][4];
#pragma unroll
    for (int i = 0; i < 4; i++)
#pragma unroll
        for (int j = 0; j < 4; j++)
#pragma unroll
            for (int r = 0; r < 4; r++) c[i][j][r] = 0.f;

    int arow = t >> 1, acol0 = (t & 1) * 8;
    int brow = t >> 4, bcol0 = (t & 15) * 8;

    float4 sa0, sa1, sbh0, sbh1, sbl0, sbl1;
    {
        const float* A = Am + (size_t)(m0 + arow) * D128 + acol0;
        sa0 = *(const float4*)A;
        sa1 = *(const float4*)(A + 4);
        const float* bhp = Bhi + (size_t)brow * D128 + bcol0;
        const float* blp = Blo + (size_t)brow * D128 + bcol0;
        sbh0 = *(const float4*)bhp;  sbh1 = *(const float4*)(bhp + 4);
        sbl0 = *(const float4*)blp;  sbl1 = *(const float4*)(blp + 4);
    }
    {
        float* buf = smem;
        float4 hv, lv;
        float* ah = buf + OF_AH + arow * ASTR + acol0;
        float* al = buf + OF_AL + arow * ASTR + acol0;
        split4(sa0, hv, lv);
        *(float4*)ah = hv; *(float4*)al = lv;
        split4(sa1, hv, lv);
        *(float4*)(ah + 4) = hv; *(float4*)(al + 4) = lv;
        float* bh = buf + OF_BH + brow * BSTR + bcol0;
        float* bl = buf + OF_BL + brow * BSTR + bcol0;
        *(float4*)bh = sbh0; *(float4*)(bh + 4) = sbh1;
        *(float4*)bl = sbl0; *(float4*)(bl + 4) = sbl1;
    }

    for (int ch = 0; ch < 16; ch++) {
        __syncthreads();
        if (ch < 15) {
            int nc = ch + 1;
            const float* A = (nc < 8)
                ? Am + (size_t)(m0 + arow) * D128 + nc * ACH + acol0
                : Ax + (size_t)(m0 + arow) * D128 + (nc - 8) * ACH + acol0;
            sa0 = *(const float4*)A;
            sa1 = *(const float4*)(A + 4);
            const float* bhp = Bhi + (size_t)(nc * ACH + brow) * D128 + bcol0;
            const float* blp = Blo + (size_t)(nc * ACH + brow) * D128 + bcol0;
            sbh0 = *(const float4*)bhp;  sbh1 = *(const float4*)(bhp + 4);
            sbl0 = *(const float4*)blp;  sbl1 = *(const float4*)(blp + 4);
        }
        const float* Ahb = smem + (ch & 1) * PBUF + OF_AH;
        const float* Alb = smem + (ch & 1) * PBUF + OF_AL;
        const float* Bhb = smem + (ch & 1) * PBUF + OF_BH;
        const float* Blb = smem + (ch & 1) * PBUF + OF_BL;
#pragma unroll
        for (int ks = 0; ks < 2; ks++) {
            uint32_t ah[4][4], bh[4][2];
#pragma unroll
            for (int mf = 0; mf < 4; mf++)
#pragma unroll
                for (int r = 0; r < 4; r++)
                    ah[mf][r] = __float_as_uint(
                        Ahb[(wm + mf * 16 + (lane >> 2) + 8 * (r & 1)) * ASTR
                            + ks * 8 + (lane & 3) + 4 * (r >> 1)]);
#pragma unroll
            for (int nf = 0; nf < 4; nf++)
#pragma unroll
                for (int r = 0; r < 2; r++)
                    bh[nf][r] = __float_as_uint(
                        Bhb[(ks * 8 + (lane & 3) + 4 * r) * BSTR + wn + nf * 8 + (lane >> 2)]);
#pragma unroll
            for (int mf = 0; mf < 4; mf++)
#pragma unroll
                for (int nf = 0; nf < 4; nf++)
                    mma_m16n8k8(c[mf][nf], ah[mf], bh[nf]);
            {
                uint32_t blo[4][2];
#pragma unroll
                for (int nf = 0; nf < 4; nf++)
#pragma unroll
                    for (int r = 0; r < 2; r++)
                        blo[nf][r] = __float_as_uint(
                            Blb[(ks * 8 + (lane & 3) + 4 * r) * BSTR + wn + nf * 8 + (lane >> 2)]);
#pragma unroll
                for (int mf = 0; mf < 4; mf++)
#pragma unroll
                    for (int nf = 0; nf < 4; nf++)
                        mma_m16n8k8(c[mf][nf], ah[mf], blo[nf]);
            }
            {
                uint32_t al[4][4];
#pragma unroll
                for (int mf = 0; mf < 4; mf++)
#pragma unroll
                    for (int r = 0; r < 4; r++)
                        al[mf][r] = __float_as_uint(
                            Alb[(wm + mf * 16 + (lane >> 2) + 8 * (r & 1)) * ASTR
                                + ks * 8 + (lane & 3) + 4 * (r >> 1)]);
#pragma unroll
                for (int mf = 0; mf < 4; mf++)
#pragma unroll
                    for (int nf = 0; nf < 4; nf++)
                        mma_m16n8k8(c[mf][nf], al[mf], bh[nf]);
            }
        }
        if (ch < 15) {
            float* buf = smem + ((ch + 1) & 1) * PBUF;
            float4 hv, lv;
            float* ah = buf + OF_AH + arow * ASTR + acol0;
            float* al = buf + OF_AL + arow * ASTR + acol0;
            split4(sa0, hv, lv);
            *(float4*)ah = hv; *(float4*)al = lv;
            split4(sa1, hv, lv);
            *(float4*)(ah + 4) = hv; *(float4*)(al + 4) = lv;
            float* bh = buf + OF_BH + brow * BSTR + bcol0;
            float* bl = buf + OF_BL + brow * BSTR + bcol0;
            *(float4*)bh = sbh0; *(float4*)(bh + 4) = sbh1;
            *(float4*)bl = sbl0; *(float4*)(bl + 4) = sbl1;
        }
    }

    int r0 = lane >> 2, cq = (lane & 3) * 2;
    float pwv[4][2];
#pragma unroll
    for (int nf = 0; nf < 4; nf++) {
        pwv[nf][0] = pw[wn + nf * 8 + cq];
        pwv[nf][1] = pw[wn + nf * 8 + cq + 1];
    }
    float* sdot = smem + OF_BH;
#pragma unroll
    for (int mf = 0; mf < 4; mf++) {
        int row = m0 + wm + mf * 16 + r0;
        float p0 = 0.f, p1 = 0.f;
#pragma unroll
        for (int nf = 0; nf < 4; nf++) {
            int col = wn + nf * 8 + cq;
            float b0 = bias[col], b1 = bias[col + 1];
            float2 o0, o1;
            o0.x = fmaxf(c[mf][nf][0] + b0, 0.f);
            o0.y = fmaxf(c[mf][nf][1] + b1, 0.f);
            o1.x = fmaxf(c[mf][nf][2] + b0, 0.f);
            o1.y = fmaxf(c[mf][nf][3] + b1, 0.f);
            *(float2*)(H + (size_t)row * D128 + col) = o0;
            *(float2*)(H + (size_t)(row + 8) * D128 + col) = o1;
            p0 += o0.x * pwv[nf][0] + o0.y * pwv[nf][1];
            p1 += o1.x * pwv[nf][0] + o1.y * pwv[nf][1];
        }
        p0 += __shfl_xor_sync(0xFFFFFFFF, p0, 1);
        p0 += __shfl_xor_sync(0xFFFFFFFF, p0, 2);
        p1 += __shfl_xor_sync(0xFFFFFFFF, p1, 1);
        p1 += __shfl_xor_sync(0xFFFFFFFF, p1, 2);
        if ((lane & 3) == 0) {
            int rr = wm + mf * 16 + r0;
            sdot[rr * 4 + (wid & 3)] = p0;
            sdot[(rr + 8) * 4 + (wid & 3)] = p1;
        }
    }
    __syncthreads();
    if (t < 128) {
        float4 d4 = *(float4*)&sdot[t * 4];
        float dot = d4.x + d4.y + d4.z + d4.w;
        score[m0 + t] = tanhf(dot * s_rnorm);
    }
}

// ---------------- tf32 mma GEMM, double-buffered, M=64 tile (frozen) ----------------
#define OF64_AH 0
#define OF64_AL (64 * ASTR)
#define OF64_BH (2 * 64 * ASTR)
#define OF64_BL (2 * 64 * ASTR + ACH * BSTR)
#define PBUF64  (2 * 64 * ASTR + 2 * ACH * BSTR)
#define GEMM64_SMEM_BYTES (2 * PBUF64 * 4)

__global__ void __launch_bounds__(256, 2)
k_gemm_mma64(const float* __restrict__ Am, const float* __restrict__ Ax,
             const float* __restrict__ Bhi, const float* __restrict__ Blo,
             const float* __restrict__ bias, const float* __restrict__ pw,
             float* __restrict__ H, float* __restrict__ score, int n) {
    extern __shared__ float smem[];
    __shared__ float s_rnorm;
    int t = threadIdx.x, lane = t & 31, wid = t >> 5;
    int wm = (wid >> 2) * 32;
    int wn = (wid & 3) * 32;
    int m0 = blockIdx.x * 64;

    if (t < 32) {
        float4 w4 = ((const float4*)pw)[t];
        float nn = w4.x * w4.x + w4.y * w4.y + w4.z * w4.z + w4.w * w4.w;
#pragma unroll
        for (int off = 16; off > 0; off >>= 1)
            nn += __shfl_xor_sync(0xFFFFFFFF, nn, off);
        if (t == 0) s_rnorm = 1.0f / sqrtf(nn);
    }

    float c[2][4][4];
#pragma unroll
    for (int i = 0; i < 2; i++)
#pragma unroll
        for (int j = 0; j < 4; j++)
#pragma unroll
            for (int r = 0; r < 4; r++) c[i][j][r] = 0.f;

    int arow = t >> 2, acol0 = (t & 3) * 4;
    int brow = t >> 4, bcol0 = (t & 15) * 8;

    float4 sa0, sbh0, sbh1, sbl0, sbl1;
    {
        sa0 = *(const float4*)(Am + (size_t)(m0 + arow) * D128 + acol0);
        const float* bhp = Bhi + (size_t)brow * D128 + bcol0;
        const float* blp = Blo + (size_t)brow * D128 + bcol0;
        sbh0 = *(const float4*)bhp;  sbh1 = *(const float4*)(bhp + 4);
        sbl0 = *(const float4*)blp;  sbl1 = *(const float4*)(blp + 4);
    }
    {
        float* buf = smem;
        float4 hv, lv;
        split4(sa0, hv, lv);
        *(float4*)(buf + OF64_AH + arow * ASTR + acol0) = hv;
        *(float4*)(buf + OF64_AL + arow * ASTR + acol0) = lv;
        float* bh = buf + OF64_BH + brow * BSTR + bcol0;
        float* bl = buf + OF64_BL + brow * BSTR + bcol0;
        *(float4*)bh = sbh0; *(float4*)(bh + 4) = sbh1;
        *(float4*)bl = sbl0; *(float4*)(bl + 4) = sbl1;
    }

    for (int ch = 0; ch < 16; ch++) {
        __syncthreads();
        if (ch < 15) {
            int nc = ch + 1;
            const float* A = (nc < 8)
                ? Am + (size_t)(m0 + arow) * D128 + nc * ACH + acol0
                : Ax + (size_t)(m0 + arow) * D128 + (nc - 8) * ACH + acol0;
            sa0 = *(const float4*)A;
            const float* bhp = Bhi + (size_t)(nc * ACH + brow) * D128 + bcol0;
            const float* blp = Blo + (size_t)(nc * ACH + brow) * D128 + bcol0;
            sbh0 = *(const float4*)bhp;  sbh1 = *(const float4*)(bhp + 4);
            sbl0 = *(const float4*)blp;  sbl1 = *(const float4*)(blp + 4);
        }
        const float* Ahb = smem + (ch & 1) * PBUF64 + OF64_AH;
        const float* Alb = smem + (ch & 1) * PBUF64 + OF64_AL;
        const float* Bhb = smem + (ch & 1) * PBUF64 + OF64_BH;
        const float* Blb = smem + (ch & 1) * PBUF64 + OF64_BL;
#pragma unroll
        for (int ks = 0; ks < 2; ks++) {
            uint32_t ah[2][4], bh[4][2];
#pragma unroll
            for (int mf = 0; mf < 2; mf++)
#pragma unroll
                for (int r = 0; r < 4; r++)
                    ah[mf][r] = __float_as_uint(
                        Ahb[(wm + mf * 16 + (lane >> 2) + 8 * (r & 1)) * ASTR
                            + ks * 8 + (lane & 3) + 4 * (r >> 1)]);
#pragma unroll
            for (int nf = 0; nf < 4; nf++)
#pragma unroll
                for (int r = 0; r < 2; r++)
                    bh[nf][r] = __float_as_uint(
                        Bhb[(ks * 8 + (lane & 3) + 4 * r) * BSTR + wn + nf * 8 + (lane >> 2)]);
#pragma unroll
            for (int mf = 0; mf < 2; mf++)
#pragma unroll
                for (int nf = 0; nf < 4; nf++)
                    mma_m16n8k8(c[mf][nf], ah[mf], bh[nf]);
            {
                uint32_t blo[4][2];
#pragma unroll
                for (int nf = 0; nf < 4; nf++)
#pragma unroll
                    for (int r = 0; r < 2; r++)
                        blo[nf][r] = __float_as_uint(
                            Blb[(ks * 8 + (lane & 3) + 4 * r) * BSTR + wn + nf * 8 + (lane >> 2)]);
#pragma unroll
                for (int mf = 0; mf < 2; mf++)
#pragma unroll
                    for (int nf = 0; nf < 4; nf++)
                        mma_m16n8k8(c[mf][nf], ah[mf], blo[nf]);
            }
            {
                uint32_t al[2][4];
#pragma unroll
                for (int mf = 0; mf < 2; mf++)
#pragma unroll
                    for (int r = 0; r < 4; r++)
                        al[mf][r] = __float_as_uint(
                            Alb[(wm + mf * 16 + (lane >> 2) + 8 * (r & 1)) * ASTR
                                + ks * 8 + (lane & 3) + 4 * (r >> 1)]);
#pragma unroll
                for (int mf = 0; mf < 2; mf++)
#pragma unroll
                    for (int nf = 0; nf < 4; nf++)
                        mma_m16n8k8(c[mf][nf], al[mf], bh[nf]);
            }
        }
        if (ch < 15) {
            float* buf = smem + ((ch + 1) & 1) * PBUF64;
            float4 hv, lv;
            split4(sa0, hv, lv);
            *(float4*)(buf + OF64_AH + arow * ASTR + acol0) = hv;
            *(float4*)(buf + OF64_AL + arow * ASTR + acol0) = lv;
            float* bh = buf + OF64_BH + brow * BSTR + bcol0;
            float* bl = buf + OF64_BL + brow * BSTR + bcol0;
            *(float4*)bh = sbh0; *(float4*)(bh + 4) = sbh1;
            *(float4*)bl = sbl0; *(float4*)(bl + 4) = sbl1;
        }
    }

    int r0 = lane >> 2, cq = (lane & 3) * 2;
    float pwv[4][2];
#pragma unroll
    for (int nf = 0; nf < 4; nf++) {
        pwv[nf][0] = pw[wn + nf * 8 + cq];
        pwv[nf][1] = pw[wn + nf * 8 + cq + 1];
    }
    float* sdot = smem + OF64_BH;
#pragma unroll
    for (int mf = 0; mf < 2; mf++) {
        int row = m0 + wm + mf * 16 + r0;
        float p0 = 0.f, p1 = 0.f;
#pragma unroll
        for (int nf = 0; nf < 4; nf++) {
            int col = wn + nf * 8 + cq;
            float b0 = bias[col], b1 = bias[col + 1];
            float2 o0, o1;
            o0.x = fmaxf(c[mf][nf][0] + b0, 0.f);
            o0.y = fmaxf(c[mf][nf][1] + b1, 0.f);
            o1.x = fmaxf(c[mf][nf][2] + b0, 0.f);
            o1.y = fmaxf(c[mf][nf][3] + b1, 0.f);
            *(float2*)(H + (size_t)row * D128 + col) = o0;
            *(float2*)(H + (size_t)(row + 8) * D128 + col) = o1;
            p0 += o0.x * pwv[nf][0] + o0.y * pwv[nf][1];
            p1 += o1.x * pwv[nf][0] + o1.y * pwv[nf][1];
        }
        p0 += __shfl_xor_sync(0xFFFFFFFF, p0, 1);
        p0 += __shfl_xor_sync(0xFFFFFFFF, p0, 2);
        p1 += __shfl_xor_sync(0xFFFFFFFF, p1, 1);
        p1 += __shfl_xor_sync(0xFFFFFFFF, p1, 2);
        if ((lane & 3) == 0) {
            int rr = wm + mf * 16 + r0;
            sdot[rr * 4 + (wid & 3)] = p0;
            sdot[(rr + 8) * 4 + (wid & 3)] = p1;
        }
    }
    __syncthreads();
    if (t < 64) {
        float4 d4 = *(float4*)&sdot[t * 4];
        float dot = d4.x + d4.y + d4.z + d4.w;
        score[m0 + t] = tanhf(dot * s_rnorm);
    }
}

// ---------------- top-K: float/int hybrid shfl/smem bitonic (R14) + fused MLP ----------------
__global__ void k_topk(const float* __restrict__ score, const float* __restrict__ H,
                       float* __restrict__ pool, int* __restrict__ newid,
                       float* __restrict__ s_out, int* __restrict__ o2c,
                       int* __restrict__ c2o, int Npg, int K, int round, int do_compose,
                       const float* __restrict__ W1, const float* __restrict__ b1,
                       const float* __restrict__ W2, const float* __restrict__ b2,
                       const float* __restrict__ W3, const float* __restrict__ b3,
                       float* __restrict__ out, int do_mlp) {
    __shared__ float skey[1024];
    __shared__ int   sidx[1024];
    __shared__ float rmx[8][128];
    __shared__ float rsm[8][128];
    __shared__ float mlp_sh[256];
    __shared__ float mlp_h1[128];
    __shared__ float mlp_h2[64];
    __shared__ float mlp_red[128];
    int g = blockIdx.x;
    int t = threadIdx.x;   // 1024 threads
    float key = (t < Npg) ? score[g * Npg + t] : -INFINITY;
    int idx = t;

    // rounds k=2..32: fully intra-warp (register + shfl, no barriers)
#pragma unroll
    for (int k = 2; k <= 32; k <<= 1) {
#pragma unroll
        for (int j = k >> 1; j > 0; j >>= 1) {
            float ok = __shfl_xor_sync(0xFFFFFFFF, key, j);
            int   oi = __shfl_xor_sync(0xFFFFFFFF, idx, j);
            bool up = ((t & j) == 0);
            bool desc = ((t & k) == 0);
            bool keep_max = (up == desc);
            bool take = keep_max ? (ok > key) : (ok < key);
            if (take) { key = ok; idx = oi; }
        }
    }
    // rounds k=64..1024: j>=32 phases in smem, j<=16 phases in registers
    for (int k = 64; k <= 1024; k <<= 1) {
        skey[t] = key; sidx[t] = idx;
        __syncthreads();
        for (int j = k >> 1; j >= 32; j >>= 1) {
            int ixj = t ^ j;
            if (ixj > t) {
                bool desc = ((t & k) == 0);
                float a = skey[t], b = skey[ixj];
                bool sw = desc ? (a < b) : (a > b);
                if (sw) {
                    skey[t] = b; skey[ixj] = a;
                    int tmp = sidx[t]; sidx[t] = sidx[ixj]; sidx[ixj] = tmp;
                }
            }
            __syncthreads();
        }
        key = skey[t]; idx = sidx[t];
#pragma unroll
        for (int j = 16; j > 0; j >>= 1) {
            float ok = __shfl_xor_sync(0xFFFFFFFF, key, j);
            int   oi = __shfl_xor_sync(0xFFFFFFFF, idx, j);
            bool up = ((t & j) == 0);
            bool desc = ((t & k) == 0);
            bool keep_max = (up == desc);
            bool take = keep_max ? (ok > key) : (ok < key);
            if (take) { key = ok; idx = oi; }
        }
    }
    skey[t] = key; sidx[t] = idx;
    __syncthreads();

    if (t < Npg) {
        int node = sidx[t];
        newid[g * Npg + node] = (t < K) ? (g * K + t) : -1;
    }
    __syncthreads();
    if (do_compose) {
        int o = g * NPG0 + t;
        int c = o2c[o];
        int nc = (c >= 0) ? newid[c] : -1;
        o2c[o] = nc;
        if (nc >= 0) c2o[nc] = o;
    }
    int f = t & 127, part = t >> 7;
    float mx = -INFINITY, sm = 0.f;
    for (int r = part; r < K; r += 8) {
        int node = sidx[r];
        float v = H[(size_t)(g * Npg + node) * D128 + f] * skey[r];
        pool[(size_t)(g * K + r) * D128 + f] = v;
        mx = fmaxf(mx, v);
        sm += v;
    }
    rmx[part][f] = mx; rsm[part][f] = sm;
    __syncthreads();
    if (t < 128) {
        float m2 = rmx[0][f], s2 = rsm[0][f];
#pragma unroll
        for (int p = 1; p < 8; p++) {
            m2 = fmaxf(m2, rmx[p][f]);
            s2 += rsm[p][f];
        }
        float mean = s2 / (float)K;
        if (round == 0) {
            s_out[g * 256 + f] = m2;
            s_out[g * 256 + 128 + f] = mean;
        } else {
            s_out[g * 256 + f] += m2;
            s_out[g * 256 + 128 + f] += mean;
        }
    }

    // ---- fused final MLP (round 2 only): 256->128->64->1 + sigmoid ----
    if (do_mlp) {
        __syncthreads();
        if (t < 128) {
            mlp_sh[t] = s_out[g * 256 + t];
            mlp_sh[t + 128] = s_out[g * 256 + 128 + t];
        }
        __syncthreads();
        if (t < 128) {
            float acc = b1[t];
            for (int k = 0; k < 256; k++) acc += mlp_sh[k] * W1[k * 128 + t];
            mlp_h1[t] = fmaxf(acc, 0.f);
        }
        __syncthreads();
        if (t < 64) {
            float a = b2[t];
            for (int k = 0; k < 128; k++) a += mlp_h1[k] * W2[k * 64 + t];
            mlp_h2[t] = fmaxf(a, 0.f);
        }
        __syncthreads();
        if (t < 128) mlp_red[t] = (t < 64) ? mlp_h2[t] * W3[t] : 0.f;
        __syncthreads();
        for (int off = 64; off > 0; off >>= 1) {
            if (t < off) mlp_red[t] += mlp_red[t + off];
            __syncthreads();
        }
        if (t == 0) out[g] = 1.f / (1.f + expf(-(mlp_red[0] + b3[0])));
    }
}

// ---------------- host orchestration ----------------
extern "C" void kernel_launch(void* const* d_in, const int* in_sizes, int n_in,
                              void* d_out, int out_size) {
    const float* x   = (const float*)d_in[0];
    const int*   ei  = (const int*)d_in[1];
    const int E = in_sizes[1] / 2;
    const int epg = E / BGR;

    const float* Wl1 = (const float*)d_in[2];
    const float* bl1 = (const float*)d_in[3];
    const float* Wr1 = (const float*)d_in[4];
    const float* pw1 = (const float*)d_in[5];
    const float* Wl2 = (const float*)d_in[6];
    const float* bl2 = (const float*)d_in[7];
    const float* Wr2 = (const float*)d_in[8];
    const float* pw2 = (const float*)d_in[9];
    const float* Wl3 = (const float*)d_in[10];
    const float* bl3 = (const float*)d_in[11];
    const float* Wr3 = (const float*)d_in[12];
    const float* pw3 = (const float*)d_in[13];
    const float* W1  = (const float*)d_in[14];
    const float* b1  = (const float*)d_in[15];
    const float* W2  = (const float*)d_in[16];
    const float* b2  = (const float*)d_in[17];
    const float* W3  = (const float*)d_in[18];
    const float* b3  = (const float*)d_in[19];

    float *meanP, *hP, *poolA, *poolB, *scoreP, *sP, *bhiP, *bloP;
    int *newidP, *o2cP, *c2oP, *rpP, *nbrP;
    cudaGetSymbolAddress((void**)&meanP, g_mean);
    cudaGetSymbolAddress((void**)&hP, g_h);
    cudaGetSymbolAddress((void**)&poolA, g_poolA);
    cudaGetSymbolAddress((void**)&poolB, g_poolB);
    cudaGetSymbolAddress((void**)&scoreP, g_score);
    cudaGetSymbolAddress((void**)&sP, g_s);
    cudaGetSymbolAddress((void**)&bhiP, g_bhi);
    cudaGetSymbolAddress((void**)&bloP, g_blo);
    cudaGetSymbolAddress((void**)&newidP, g_newid);
    cudaGetSymbolAddress((void**)&o2cP, g_orig2cur);
    cudaGetSymbolAddress((void**)&c2oP, g_cur2orig);
    cudaGetSymbolAddress((void**)&rpP, g_rowptr);
    cudaGetSymbolAddress((void**)&nbrP, g_nbr);

    cudaFuncSetAttribute(k_gemm_mma, cudaFuncAttributeMaxDynamicSharedMemorySize,
                         GEMM_SMEM_BYTES);
    cudaFuncSetAttribute(k_gemm_mma64, cudaFuncAttributeMaxDynamicSharedMemorySize,
                         GEMM64_SMEM_BYTES);

    const int TB = 256;

    // one-time: CSR + map init + weight split in a single launch
    k_init<<<BGR + 96, 1024>>>(ei, ei + E, epg, rpP, nbrP, o2cP, c2oP,
                               Wl1, Wr1, Wl2, Wr2, Wl3, Wr3, bhiP, bloP);

    struct LayerCfg {
        const float *xin, *bl, *pw;
        float* pool;
        int n, Npg, K, round;
    };
    LayerCfg layers[3] = {
        { x,     bl1, pw1, poolA, BGR * NPG0, NPG0, K1, 0 },
        { poolA, bl2, pw2, poolB, BGR * K1,   K1,   K2, 1 },
        { poolB, bl3, pw3, poolA, BGR * K2,   K2,   K3, 2 },
    };

    for (int L = 0; L < 3; L++) {
        LayerCfg& c = layers[L];
        int n = c.n;
        if (L == 0)
            k_aggregate1<<<(n * 32 + TB - 1) / TB, TB>>>(c.xin, rpP, nbrP, meanP, n);
        else
            k_aggregate<<<(n * 32 + TB - 1) / TB, TB>>>(c.xin, rpP, nbrP, c2oP, o2cP, meanP, n);
        if (L == 0)
            k_gemm_mma<<<n / 128, 256, GEMM_SMEM_BYTES>>>(
                meanP, c.xin, bhiP + L * 256 * D128, bloP + L * 256 * D128,
                c.bl, c.pw, hP, scoreP, n);
        else
            k_gemm_mma64<<<n / 64, 256, GEMM64_SMEM_BYTES>>>(
                meanP, c.xin, bhiP + L * 256 * D128, bloP + L * 256 * D128,
                c.bl, c.pw, hP, scoreP, n);
        k_topk<<<BGR, 1024>>>(scoreP, hP, c.pool, newidP, sP, o2cP, c2oP,
                              c.Npg, c.K, c.round, (L < 2) ? 1 : 0,
                              W1, b1, W2, b2, W3, b3, (float*)d_out,
                              (L == 2) ? 1 : 0);
    }
}